// round 2
// baseline (speedup 1.0000x reference)
#include <cuda_runtime.h>
#include <cuda_bf16.h>

#define FULL_MASK 0xFFFFFFFFu

// One warp per OFDM row (row = 64 complex samples, stored as [2][64] floats).
// Radix-2 DIF FFT across the warp: lane l holds virtual indices l (reg a) and
// l+32 (reg b). After 6 stages, storage s = 32*reg + lane holds F[bitrev6(s)].
// Register a holds even k = bitrev6(lane); register b holds k+1.
// Pilots k={11,25,39,53} live at bitrev positions {52,38,57,43} -> reg b,
// lanes {20,6,25,11}.

__global__ __launch_bounds__(256) void ofdm_fft_eq_kernel(
    const float* __restrict__ x, float* __restrict__ out, int nrows)
{
    const int lane   = threadIdx.x & 31;
    const int gwarp  = (blockIdx.x * blockDim.x + threadIdx.x) >> 5;
    const int nwarps = (gridDim.x * blockDim.x) >> 5;

    const float PI32 = 0.09817477042468103f; // pi/32

    // ---- Hoisted per-lane constants (identical for every row) ----
    // Stage h=32 twiddle: W64^lane = cos(t) - i sin(t); computed as sincos(-t).
    float c32, s32;
    __sincosf(-(float)lane * PI32, &s32, &c32);

    // Cross-lane stages h=16,8,4,2,1: twiddle applied only on "upper" lane.
    float ce[5], se[5], sgn[5];
    {
        int h = 16;
        #pragma unroll
        for (int st = 0; st < 5; ++st) {
            int t = (lane & (h - 1)) * (32 / h);
            float s, c;
            __sincosf(-(float)t * PI32, &s, &c);
            bool up = (lane & h) != 0;
            ce[st] = up ? c : 1.0f;
            se[st] = up ? s : 0.0f;
            sgn[st] = up ? -1.0f : 1.0f;
            h >>= 1;
        }
    }

    const int ka = (int)(__brev((unsigned)lane) >> 26); // even k held in reg a

    for (int row = gwarp; row < nrows; row += nwarps) {
        const float* px = x   + (size_t)row * 128;
        float*       po = out + (size_t)row * 128;

        // ---- Load (fully coalesced 4B) ----
        float ar = px[lane];
        float br = px[lane + 32];
        float ai = px[64 + lane];
        float bi = px[96 + lane];

        // ---- Stage h=32 (lane-local butterfly) ----
        {
            float tr = ar - br, ti = ai - bi;
            ar += br; ai += bi;
            br = tr * c32 - ti * s32;
            bi = tr * s32 + ti * c32;
        }

        // ---- Stages h=16,8,4,2,1 (shuffle butterflies) ----
        {
            int h = 16;
            #pragma unroll
            for (int st = 0; st < 5; ++st) {
                float g = sgn[st], cc = ce[st], ss = se[st];

                float oar = __shfl_xor_sync(FULL_MASK, ar, h);
                float oai = __shfl_xor_sync(FULL_MASK, ai, h);
                float ur = fmaf(g, ar, oar);   // up: other-mine, down: mine+other
                float ui = fmaf(g, ai, oai);
                ar = ur * cc - ui * ss;
                ai = ur * ss + ui * cc;

                float obr = __shfl_xor_sync(FULL_MASK, br, h);
                float obi = __shfl_xor_sync(FULL_MASK, bi, h);
                float vr = fmaf(g, br, obr);
                float vi = fmaf(g, bi, obi);
                br = vr * cc - vi * ss;
                bi = vr * ss + vi * cc;

                h >>= 1;
            }
        }

        // ---- Broadcast pilot frequency values (all live in reg b) ----
        float h0r = __shfl_sync(FULL_MASK, br, 20), h0i = __shfl_sync(FULL_MASK, bi, 20); // k=11
        float h1r = __shfl_sync(FULL_MASK, br,  6), h1i = __shfl_sync(FULL_MASK, bi,  6); // k=25
        float h2r = __shfl_sync(FULL_MASK, br, 25), h2i = __shfl_sync(FULL_MASK, bi, 25); // k=39
        float h3r = __shfl_sync(FULL_MASK, br, 11), h3i = __shfl_sync(FULL_MASK, bi, 11); // k=53

        // ---- Equalize both held bins (k = ka and ka+1) ----
        float eout[4]; // ear, ebr, eai, ebi
        #pragma unroll
        for (int v = 0; v < 2; ++v) {
            int k = ka + v;
            float fr = v ? br : ar;
            float fi = v ? bi : ai;

            // Piecewise-linear pilot interpolation (pilot spacing = 14)
            float p = (float)(k - 11) * (1.0f / 14.0f);
            p = fminf(fmaxf(p, 0.0f), 3.0f);
            float segf = floorf(p);
            if (segf > 2.0f) segf = 2.0f;
            int seg = (int)segf;
            float al = p - segf;

            float lr = (seg == 0) ? h0r : ((seg == 1) ? h1r : h2r);
            float li = (seg == 0) ? h0i : ((seg == 1) ? h1i : h2i);
            float rr = (seg == 0) ? h1r : ((seg == 1) ? h2r : h3r);
            float ri = (seg == 0) ? h1i : ((seg == 1) ? h2i : h3i);

            float hr = fmaf(rr - lr, al, lr);
            float hi = fmaf(ri - li, al, li);

            float den = fmaf(hr, hr, fmaf(hi, hi, 1e-8f));
            float inv = __fdividef(1.0f, den);
            eout[v]     = (fr * hr + fi * hi) * inv; // eq_r
            eout[2 + v] = (fi * hr - fr * hi) * inv; // eq_i
        }

        // ---- Store: adjacent bins -> vectorized 8B stores (ka even) ----
        *reinterpret_cast<float2*>(po + ka)      = make_float2(eout[0], eout[1]);
        *reinterpret_cast<float2*>(po + 64 + ka) = make_float2(eout[2], eout[3]);
    }
}

extern "C" void kernel_launch(void* const* d_in, const int* in_sizes, int n_in,
                              void* d_out, int out_size) {
    const float* x = (const float*)d_in[0];
    float* out = (float*)d_out;
    int nrows = in_sizes[0] / 128; // 262144

    // 4096 blocks x 8 warps = 32768 warps -> 8 rows per warp; grid-stride safe.
    int blocks = 4096;
    ofdm_fft_eq_kernel<<<blocks, 256>>>(x, out, nrows);
}